// round 10
// baseline (speedup 1.0000x reference)
#include <cuda_runtime.h>

// Fast Hadamard Transform, DIM = 4096, fp32 — single-SMEM-trip version.
// (Champion body; finer CTA granularity: 1 row per 64-thread CTA.)
//
// 64 threads per row, 64 elements per thread, two FWHT-64 register passes:
//   pass 1 over element bits {0,1,8,9,10,11}  (float4-coalesced __ldcg loads)
//   pass 2 over element bits {2..7}           (one swizzled SMEM exchange)
// then a 3-bit register<->lane shuffle transpose (i[2..4] <-> i[8..10])
// so the final stores are fully coalesced (__stcs).
//
// 64-thread CTAs: 10 CTAs/SM (20 warps) -> 10 independent front-batched load
// streams per SM and half-length waves (finer tail), same per-row code.

#define FWHT_DIM 4096
#define THREADS 64

// scale = 2^-(L(L+1)/4) with L=12 -> 2^-39
#define FWHT_SCALE 0x1p-39f

__device__ __forceinline__ void fwht64(float r[64]) {
#pragma unroll
    for (int h = 1; h < 64; h <<= 1) {
#pragma unroll
        for (int k = 0; k < 64; k++) {
            if (!(k & h)) {
                float a = r[k];
                float b = r[k ^ h];
                r[k]     = a + b;
                r[k ^ h] = a - b;
            }
        }
    }
}

// Swap register-index bit `rb` with lane bit `lb`.
#define SWAPBIT(r, lane, rb, lb)                                               \
    do {                                                                       \
        const unsigned _lm = 1u << (lb);                                       \
        const bool _hi = ((lane) & _lm) != 0;                                  \
        _Pragma("unroll")                                                      \
        for (int _k = 0; _k < 64; _k++) {                                      \
            if (!(_k & (1 << (rb)))) {                                         \
                const int _k2 = _k | (1 << (rb));                              \
                float _send = _hi ? (r)[_k] : (r)[_k2];                        \
                float _recv = __shfl_xor_sync(0xffffffffu, _send, _lm, 32);    \
                if (_hi) (r)[_k] = _recv; else (r)[_k2] = _recv;               \
            }                                                                  \
        }                                                                      \
    } while (0)

__global__ void __launch_bounds__(THREADS)
fwht4096_kernel(const float* __restrict__ x, float* __restrict__ out) {
    __shared__ float s[FWHT_DIM];   // 16 KB, one row

    const int t    = threadIdx.x;        // 0..63
    const int lane = t & 31;             // lane within warp
    const int w    = t >> 5;             // warp within row (= element bit 11)

    const size_t row = (size_t)blockIdx.x;
    const float* __restrict__ xr = x + row * FWHT_DIM;
    float* __restrict__ yr = out + row * FWHT_DIM;

    float r[64];

    // ---- Pass 1: bits {0,1,8,9,10,11}. r[p*4+q] = x[p*256 + t*4 + q] ----
    // 16 independent LDG.128 (.cg: streaming input, skip L1 allocation).
#pragma unroll
    for (int p = 0; p < 16; p++) {
        float4 v = __ldcg(reinterpret_cast<const float4*>(xr + p * 256 + t * 4));
        r[p * 4 + 0] = v.x;
        r[p * 4 + 1] = v.y;
        r[p * 4 + 2] = v.z;
        r[p * 4 + 3] = v.w;
    }
    fwht64(r);   // reg index j = (p<<2)|q covers element bits {8..11,0,1}

    // ---- SMEM write: STS.128, XOR-swizzled (conflict-free) ----
    // float addr a = p*256 + t*4 + q ; phys = a ^ ((p&7)<<2)
#pragma unroll
    for (int p = 0; p < 16; p++) {
        int a0   = p * 256 + t * 4;
        int phys = a0 ^ ((p & 7) << 2);
        *reinterpret_cast<float4*>(s + phys) =
            make_float4(r[p * 4 + 0], r[p * 4 + 1], r[p * 4 + 2], r[p * 4 + 3]);
    }
    __syncthreads();

    // ---- SMEM read for pass 2: thread owns bits {2..7} varying ----
    // a = th*256 + j*4 + tl ; phys = a ^ ((th&7)<<2): banks all distinct.
    {
        const int th    = t >> 2;
        const int tl    = t & 3;
        const int base2 = th * 256 + tl;
        const int c     = (th & 7) << 2;
#pragma unroll
        for (int j = 0; j < 64; j++) {
            r[j] = s[base2 + ((j * 4) ^ c)];
        }
    }
    fwht64(r);   // reg index j' = i[7:2] covers element bits {2..7}

    // ---- Scale ----
#pragma unroll
    for (int j = 0; j < 64; j++) r[j] *= FWHT_SCALE;

    // ---- Shuffle transpose: swap i[2]<->i[8], i[3]<->i[9], i[4]<->i[10] ----
    SWAPBIT(r, lane, 0, 2);
    SWAPBIT(r, lane, 1, 3);
    SWAPBIT(r, lane, 2, 4);

    // ---- Coalesced streaming stores (evict-first) ----
    // Post-swap reg k: k[2:0] = i[10:8], k[5:3] = i[7:5]; lane = i[4:0]; w = i[11].
    // m = i[10:5] = ((k&7)<<3) | (k>>3). Each STG.32 inst writes 128B contiguous.
    {
        float* __restrict__ yw = yr + w * 2048 + lane;
#pragma unroll
        for (int k = 0; k < 64; k++) {
            const int m = ((k & 7) << 3) | (k >> 3);
            __stcs(yw + m * 32, r[k]);
        }
    }
}

extern "C" void kernel_launch(void* const* d_in, const int* in_sizes, int n_in,
                              void* d_out, int out_size) {
    const float* x = (const float*)d_in[0];
    float* out = (float*)d_out;
    const int rows = in_sizes[0] / FWHT_DIM;   // 8192
    fwht4096_kernel<<<rows, THREADS>>>(x, out);
}

// round 11
// speedup vs baseline: 1.1225x; 1.1225x over previous
#include <cuda_runtime.h>

// Fast Hadamard Transform, DIM = 4096, fp32 — single-SMEM-trip version.
// (R2 champion structure, unchanged; inverted L2 cache policy.)
//
// 64 threads per row, 64 elements per thread, two FWHT-64 register passes:
//   pass 1 over element bits {0,1,8,9,10,11}  (float4-coalesced __ldcs loads)
//   pass 2 over element bits {2..7}           (one swizzled SMEM exchange)
// then a 3-bit register<->lane shuffle transpose (i[2..4] <-> i[8..10])
// so the final stores are fully coalesced.
//
// Cache policy (steady-state graph replay): the 134MB output nearly fits in
// 126MB L2 and is overwritten every replay — dirty output lines that survive
// in L2 until the next replay never cost a DRAM writeback. So:
//   loads : __ldcs (evict-first — input read once, must not displace output)
//   stores: default .wb   (let output accumulate dirty in L2)

#define FWHT_DIM 4096
#define ROWS_PER_CTA 2
#define THREADS (64 * ROWS_PER_CTA)   // 128

// scale = 2^-(L(L+1)/4) with L=12 -> 2^-39
#define FWHT_SCALE 0x1p-39f

__device__ __forceinline__ void fwht64(float r[64]) {
#pragma unroll
    for (int h = 1; h < 64; h <<= 1) {
#pragma unroll
        for (int k = 0; k < 64; k++) {
            if (!(k & h)) {
                float a = r[k];
                float b = r[k ^ h];
                r[k]     = a + b;
                r[k ^ h] = a - b;
            }
        }
    }
}

// Swap register-index bit `rb` with lane bit `lb`.
#define SWAPBIT(r, lane, rb, lb)                                               \
    do {                                                                       \
        const unsigned _lm = 1u << (lb);                                       \
        const bool _hi = ((lane) & _lm) != 0;                                  \
        _Pragma("unroll")                                                      \
        for (int _k = 0; _k < 64; _k++) {                                      \
            if (!(_k & (1 << (rb)))) {                                         \
                const int _k2 = _k | (1 << (rb));                              \
                float _send = _hi ? (r)[_k] : (r)[_k2];                        \
                float _recv = __shfl_xor_sync(0xffffffffu, _send, _lm, 32);    \
                if (_hi) (r)[_k] = _recv; else (r)[_k2] = _recv;               \
            }                                                                  \
        }                                                                      \
    } while (0)

__global__ void __launch_bounds__(THREADS)
fwht4096_kernel(const float* __restrict__ x, float* __restrict__ out) {
    __shared__ float s[ROWS_PER_CTA * FWHT_DIM];   // 32 KB

    const int tid      = threadIdx.x;
    const int rowInCta = tid >> 6;       // which of the 2 rows
    const int t        = tid & 63;       // thread within row
    const int lane     = tid & 31;       // lane within warp
    const int w        = (t >> 5) & 1;   // warp within row (= element bit 11)

    const size_t row = (size_t)blockIdx.x * ROWS_PER_CTA + rowInCta;
    const float* __restrict__ xr = x + row * FWHT_DIM;
    float* __restrict__ yr = out + row * FWHT_DIM;
    float* __restrict__ sr = s + rowInCta * FWHT_DIM;

    float r[64];

    // ---- Pass 1: bits {0,1,8,9,10,11}. r[p*4+q] = x[p*256 + t*4 + q] ----
    // 16 independent LDG.128 (.cs: streaming input, evict-first in L2).
#pragma unroll
    for (int p = 0; p < 16; p++) {
        float4 v = __ldcs(reinterpret_cast<const float4*>(xr + p * 256 + t * 4));
        r[p * 4 + 0] = v.x;
        r[p * 4 + 1] = v.y;
        r[p * 4 + 2] = v.z;
        r[p * 4 + 3] = v.w;
    }
    fwht64(r);   // reg index j = (p<<2)|q covers element bits {8..11,0,1}

    // ---- SMEM write: STS.128, XOR-swizzled (conflict-free) ----
    // float addr a = p*256 + t*4 + q ; phys = a ^ ((p&7)<<2)
#pragma unroll
    for (int p = 0; p < 16; p++) {
        int a0   = p * 256 + t * 4;
        int phys = a0 ^ ((p & 7) << 2);
        *reinterpret_cast<float4*>(sr + phys) =
            make_float4(r[p * 4 + 0], r[p * 4 + 1], r[p * 4 + 2], r[p * 4 + 3]);
    }
    __syncthreads();

    // ---- SMEM read for pass 2: thread owns bits {2..7} varying ----
    // a = th*256 + j*4 + tl ; phys = a ^ ((th&7)<<2): banks all distinct.
    {
        const int th    = t >> 2;
        const int tl    = t & 3;
        const int base2 = th * 256 + tl;
        const int c     = (th & 7) << 2;
#pragma unroll
        for (int j = 0; j < 64; j++) {
            r[j] = sr[base2 + ((j * 4) ^ c)];
        }
    }
    fwht64(r);   // reg index j' = i[7:2] covers element bits {2..7}

    // ---- Scale ----
#pragma unroll
    for (int j = 0; j < 64; j++) r[j] *= FWHT_SCALE;

    // ---- Shuffle transpose: swap i[2]<->i[8], i[3]<->i[9], i[4]<->i[10] ----
    SWAPBIT(r, lane, 0, 2);
    SWAPBIT(r, lane, 1, 3);
    SWAPBIT(r, lane, 2, 4);

    // ---- Coalesced stores (default .wb — keep output dirty in L2) ----
    // Post-swap reg k: k[2:0] = i[10:8], k[5:3] = i[7:5]; lane = i[4:0]; w = i[11].
    // m = i[10:5] = ((k&7)<<3) | (k>>3). Each STG.32 inst writes 128B contiguous.
    {
        float* __restrict__ yw = yr + w * 2048 + lane;
#pragma unroll
        for (int k = 0; k < 64; k++) {
            const int m = ((k & 7) << 3) | (k >> 3);
            yw[m * 32] = r[k];
        }
    }
}

extern "C" void kernel_launch(void* const* d_in, const int* in_sizes, int n_in,
                              void* d_out, int out_size) {
    const float* x = (const float*)d_in[0];
    float* out = (float*)d_out;
    const int rows = in_sizes[0] / FWHT_DIM;   // 8192
    fwht4096_kernel<<<rows / ROWS_PER_CTA, THREADS>>>(x, out);
}

// round 12
// speedup vs baseline: 1.1722x; 1.0443x over previous
#include <cuda_runtime.h>

// Fast Hadamard Transform, DIM = 4096, fp32 — single-SMEM-trip version.
// (Champion structure; final cache-policy cell: __ldcg loads + default stores.)
//
// 64 threads per row, 64 elements per thread, two FWHT-64 register passes:
//   pass 1 over element bits {0,1,8,9,10,11}  (float4-coalesced __ldcg loads)
//   pass 2 over element bits {2..7}           (one swizzled SMEM exchange)
// then a 3-bit register<->lane shuffle transpose (i[2..4] <-> i[8..10])
// so the final stores are fully coalesced (default .wb).

#define FWHT_DIM 4096
#define ROWS_PER_CTA 2
#define THREADS (64 * ROWS_PER_CTA)   // 128

// scale = 2^-(L(L+1)/4) with L=12 -> 2^-39
#define FWHT_SCALE 0x1p-39f

__device__ __forceinline__ void fwht64(float r[64]) {
#pragma unroll
    for (int h = 1; h < 64; h <<= 1) {
#pragma unroll
        for (int k = 0; k < 64; k++) {
            if (!(k & h)) {
                float a = r[k];
                float b = r[k ^ h];
                r[k]     = a + b;
                r[k ^ h] = a - b;
            }
        }
    }
}

// Swap register-index bit `rb` with lane bit `lb`.
#define SWAPBIT(r, lane, rb, lb)                                               \
    do {                                                                       \
        const unsigned _lm = 1u << (lb);                                       \
        const bool _hi = ((lane) & _lm) != 0;                                  \
        _Pragma("unroll")                                                      \
        for (int _k = 0; _k < 64; _k++) {                                      \
            if (!(_k & (1 << (rb)))) {                                         \
                const int _k2 = _k | (1 << (rb));                              \
                float _send = _hi ? (r)[_k] : (r)[_k2];                        \
                float _recv = __shfl_xor_sync(0xffffffffu, _send, _lm, 32);    \
                if (_hi) (r)[_k] = _recv; else (r)[_k2] = _recv;               \
            }                                                                  \
        }                                                                      \
    } while (0)

__global__ void __launch_bounds__(THREADS)
fwht4096_kernel(const float* __restrict__ x, float* __restrict__ out) {
    __shared__ float s[ROWS_PER_CTA * FWHT_DIM];   // 32 KB

    const int tid      = threadIdx.x;
    const int rowInCta = tid >> 6;       // which of the 2 rows
    const int t        = tid & 63;       // thread within row
    const int lane     = tid & 31;       // lane within warp
    const int w        = (t >> 5) & 1;   // warp within row (= element bit 11)

    const size_t row = (size_t)blockIdx.x * ROWS_PER_CTA + rowInCta;
    const float* __restrict__ xr = x + row * FWHT_DIM;
    float* __restrict__ yr = out + row * FWHT_DIM;
    float* __restrict__ sr = s + rowInCta * FWHT_DIM;

    float r[64];

    // ---- Pass 1: bits {0,1,8,9,10,11}. r[p*4+q] = x[p*256 + t*4 + q] ----
    // 16 independent LDG.128 (.cg: streaming input, skip L1 allocation;
    // normal L2 priority).
#pragma unroll
    for (int p = 0; p < 16; p++) {
        float4 v = __ldcg(reinterpret_cast<const float4*>(xr + p * 256 + t * 4));
        r[p * 4 + 0] = v.x;
        r[p * 4 + 1] = v.y;
        r[p * 4 + 2] = v.z;
        r[p * 4 + 3] = v.w;
    }
    fwht64(r);   // reg index j = (p<<2)|q covers element bits {8..11,0,1}

    // ---- SMEM write: STS.128, XOR-swizzled (conflict-free) ----
    // float addr a = p*256 + t*4 + q ; phys = a ^ ((p&7)<<2)
#pragma unroll
    for (int p = 0; p < 16; p++) {
        int a0   = p * 256 + t * 4;
        int phys = a0 ^ ((p & 7) << 2);
        *reinterpret_cast<float4*>(sr + phys) =
            make_float4(r[p * 4 + 0], r[p * 4 + 1], r[p * 4 + 2], r[p * 4 + 3]);
    }
    __syncthreads();

    // ---- SMEM read for pass 2: thread owns bits {2..7} varying ----
    // a = th*256 + j*4 + tl ; phys = a ^ ((th&7)<<2): banks all distinct.
    {
        const int th    = t >> 2;
        const int tl    = t & 3;
        const int base2 = th * 256 + tl;
        const int c     = (th & 7) << 2;
#pragma unroll
        for (int j = 0; j < 64; j++) {
            r[j] = sr[base2 + ((j * 4) ^ c)];
        }
    }
    fwht64(r);   // reg index j' = i[7:2] covers element bits {2..7}

    // ---- Scale ----
#pragma unroll
    for (int j = 0; j < 64; j++) r[j] *= FWHT_SCALE;

    // ---- Shuffle transpose: swap i[2]<->i[8], i[3]<->i[9], i[4]<->i[10] ----
    SWAPBIT(r, lane, 0, 2);
    SWAPBIT(r, lane, 1, 3);
    SWAPBIT(r, lane, 2, 4);

    // ---- Coalesced stores (default .wb) ----
    // Post-swap reg k: k[2:0] = i[10:8], k[5:3] = i[7:5]; lane = i[4:0]; w = i[11].
    // m = i[10:5] = ((k&7)<<3) | (k>>3). Each STG.32 inst writes 128B contiguous.
    {
        float* __restrict__ yw = yr + w * 2048 + lane;
#pragma unroll
        for (int k = 0; k < 64; k++) {
            const int m = ((k & 7) << 3) | (k >> 3);
            yw[m * 32] = r[k];
        }
    }
}

extern "C" void kernel_launch(void* const* d_in, const int* in_sizes, int n_in,
                              void* d_out, int out_size) {
    const float* x = (const float*)d_in[0];
    float* out = (float*)d_out;
    const int rows = in_sizes[0] / FWHT_DIM;   // 8192
    fwht4096_kernel<<<rows / ROWS_PER_CTA, THREADS>>>(x, out);
}